// round 4
// baseline (speedup 1.0000x reference)
#include <cuda_runtime.h>
#include <math.h>

// Problem constants
#define D    512
#define BB   64
#define TSRC 48
#define TTGT 48
#define VDE  32000
#define S    (BB * D)        // 32768 = one (B,D) state
#define M3   (TSRC * BB)     // 3072 rows
#define NCTA 128

// ---------------- scratch (device globals; no allocation allowed) ------------
__device__ float g_Wcat[1536 * D];       // [Wz;Wr;Wn] rows, NT layout
__device__ float g_bcat[1536];
__device__ float g_Ut[D * D];            // U transposed: Ut[j][k] = U[k][j]
__device__ float g_Genc[M3 * 1536];      // precomputed x-gates (encoder layer1)
__device__ float g_Gdec[M3 * 1536];      // precomputed x-gates (decoder)
__device__ float g_h1[2 * S];            // encoder layer1 state (double buffer)
__device__ float g_h2[2 * S];            // encoder layer2 / decoder state
__device__ float g_H[TSRC * S];          // encoder outputs per step [t][b][d]
__device__ float g_hall[TTGT * S];       // decoder h per step
__device__ float g_ctx[TTGT * S];        // attention context per step
__device__ float g_out[TTGT * S];        // h + ctx@Wctx^T

// grid-barrier state (zero-init; reset at end of every recurrence run)
__device__ unsigned g_flags[NCTA];
__device__ unsigned g_relgen;

// ---------------------------------------------------------------------------
// L2-coherent loads for cross-SM recurrent state
// ---------------------------------------------------------------------------
__device__ __forceinline__ float4 ldcg4(const float* p) {
    float4 v;
    asm volatile("ld.global.cg.v4.f32 {%0,%1,%2,%3}, [%4];"
                 : "=f"(v.x), "=f"(v.y), "=f"(v.z), "=f"(v.w) : "l"(p));
    return v;
}
__device__ __forceinline__ float ldcg1(const float* p) {
    float v;
    asm volatile("ld.global.cg.f32 %0, [%1];" : "=f"(v) : "l"(p));
    return v;
}

// ---------------------------------------------------------------------------
// tf32 tensor-core NT GEMM (unchanged from round 3)
// ---------------------------------------------------------------------------
__device__ __forceinline__ unsigned f2tf32(float x) {
    unsigned r;
    asm("cvt.rna.tf32.f32 %0, %1;" : "=r"(r) : "f"(x));
    return r;
}

__global__ __launch_bounds__(256) void sgemm_tf32(
    const float* __restrict__ A, const int* __restrict__ ids,
    const float* __restrict__ E, const float* __restrict__ Bm,
    const float* __restrict__ bias, const float* __restrict__ addend,
    float* __restrict__ C, int M, int N, int K)
{
    __shared__ unsigned As[128 * 36];
    __shared__ unsigned Bs[128 * 36];

    const int tid  = threadIdx.x;
    const int lane = tid & 31;
    const int warp = tid >> 5;
    const int row0 = blockIdx.y * 128;
    const int col0 = blockIdx.x * 128;

    const int mwarp = (warp >> 2) * 64;
    const int nwarp = (warp & 3) * 32;
    const int gid = lane >> 2;
    const int tig = lane & 3;

    const int lr = tid >> 3;
    const int lc = (tid & 7) * 4;

    const float* aPtr[4];
    const float* bPtr[4];
#pragma unroll
    for (int i = 0; i < 4; i++) {
        int r = row0 + lr + 32 * i;
        aPtr[i] = ids ? (E + (size_t)ids[r] * K) : (A + (size_t)r * K);
        bPtr[i] = Bm + (size_t)(col0 + lr + 32 * i) * K;
    }

    float acc[4][4][4];
#pragma unroll
    for (int mt = 0; mt < 4; mt++)
#pragma unroll
        for (int nt = 0; nt < 4; nt++)
#pragma unroll
            for (int q = 0; q < 4; q++) acc[mt][nt][q] = 0.f;

    const int kchunks = K >> 5;
    float4 aReg[4], bReg[4];
#pragma unroll
    for (int i = 0; i < 4; i++) {
        aReg[i] = *(const float4*)(aPtr[i] + lc);
        bReg[i] = *(const float4*)(bPtr[i] + lc);
    }

    for (int ch = 0; ch < kchunks; ch++) {
#pragma unroll
        for (int i = 0; i < 4; i++) {
            int base = (lr + 32 * i) * 36 + lc;
            uint4 av, bv;
            av.x = f2tf32(aReg[i].x); av.y = f2tf32(aReg[i].y);
            av.z = f2tf32(aReg[i].z); av.w = f2tf32(aReg[i].w);
            bv.x = f2tf32(bReg[i].x); bv.y = f2tf32(bReg[i].y);
            bv.z = f2tf32(bReg[i].z); bv.w = f2tf32(bReg[i].w);
            *(uint4*)&As[base] = av;
            *(uint4*)&Bs[base] = bv;
        }
        __syncthreads();

        if (ch + 1 < kchunks) {
            int koff = (ch + 1) * 32 + lc;
#pragma unroll
            for (int i = 0; i < 4; i++) {
                aReg[i] = *(const float4*)(aPtr[i] + koff);
                bReg[i] = *(const float4*)(bPtr[i] + koff);
            }
        }

#pragma unroll
        for (int ks = 0; ks < 4; ks++) {
            int k0 = ks * 8;
            unsigned bf[4][2];
#pragma unroll
            for (int nt = 0; nt < 4; nt++) {
                int nb = nwarp + nt * 8 + gid;
                bf[nt][0] = Bs[nb * 36 + k0 + tig];
                bf[nt][1] = Bs[nb * 36 + k0 + tig + 4];
            }
#pragma unroll
            for (int mt = 0; mt < 4; mt++) {
                int rm = mwarp + mt * 16 + gid;
                unsigned a0 = As[rm * 36 + k0 + tig];
                unsigned a1 = As[(rm + 8) * 36 + k0 + tig];
                unsigned a2 = As[rm * 36 + k0 + tig + 4];
                unsigned a3 = As[(rm + 8) * 36 + k0 + tig + 4];
#pragma unroll
                for (int nt = 0; nt < 4; nt++) {
                    asm volatile(
                        "mma.sync.aligned.m16n8k8.row.col.f32.tf32.tf32.f32 "
                        "{%0,%1,%2,%3}, {%4,%5,%6,%7}, {%8,%9}, {%0,%1,%2,%3};"
                        : "+f"(acc[mt][nt][0]), "+f"(acc[mt][nt][1]),
                          "+f"(acc[mt][nt][2]), "+f"(acc[mt][nt][3])
                        : "r"(a0), "r"(a1), "r"(a2), "r"(a3),
                          "r"(bf[nt][0]), "r"(bf[nt][1]));
                }
            }
        }
        __syncthreads();
    }

#pragma unroll
    for (int mt = 0; mt < 4; mt++) {
        int r = row0 + mwarp + mt * 16 + gid;
#pragma unroll
        for (int nt = 0; nt < 4; nt++) {
            int c = col0 + nwarp + nt * 8 + tig * 2;
            float v0 = acc[mt][nt][0], v1 = acc[mt][nt][1];
            float v2 = acc[mt][nt][2], v3 = acc[mt][nt][3];
            if (bias) {
                float b0 = bias[c], b1 = bias[c + 1];
                v0 += b0; v1 += b1; v2 += b0; v3 += b1;
            }
            if (addend) {
                float2 a0 = *(const float2*)&addend[(size_t)r * N + c];
                float2 a1 = *(const float2*)&addend[(size_t)(r + 8) * N + c];
                v0 += a0.x; v1 += a0.y; v2 += a1.x; v3 += a1.y;
            }
            float2 o0; o0.x = v0; o0.y = v1;
            float2 o1; o1.x = v2; o1.y = v3;
            *(float2*)&C[(size_t)r * N + c] = o0;
            *(float2*)&C[(size_t)(r + 8) * N + c] = o1;
        }
    }
}

// ---------------------------------------------------------------------------
__global__ void build_wcat(const float* __restrict__ Wz, const float* __restrict__ bz,
                           const float* __restrict__ Wr, const float* __restrict__ br,
                           const float* __restrict__ Wn, const float* __restrict__ bn)
{
    int idx = blockIdx.x * blockDim.x + threadIdx.x;
    if (idx >= 1536 * D) return;
    int j = idx / D, k = idx % D;
    int g = j >> 9, jr = j & 511;
    const float* W = (g == 0) ? Wz : (g == 1) ? Wr : Wn;
    g_Wcat[idx] = W[jr * D + k];
    if (k == 0) {
        const float* bvec = (g == 0) ? bz : (g == 1) ? br : bn;
        g_bcat[j] = bvec[jr];
    }
}

// Ut[j][k] = U[k][j]
__global__ void transpose512(const float* __restrict__ U, float* __restrict__ Ut)
{
    __shared__ float tile[32][33];
    int k0 = blockIdx.y * 32;
    int j0 = blockIdx.x * 32;
    int tx = threadIdx.x, ty = threadIdx.y;
#pragma unroll
    for (int i = 0; i < 4; i++)
        tile[ty + i * 8][tx] = U[(size_t)(k0 + ty + i * 8) * D + j0 + tx];
    __syncthreads();
#pragma unroll
    for (int i = 0; i < 4; i++)
        Ut[(size_t)(j0 + ty + i * 8) * D + k0 + tx] = tile[tx][ty + i * 8];
}

__global__ void zero2(float* a, float* b, int n)
{
    int i = blockIdx.x * blockDim.x + threadIdx.x;
    if (i < n) { a[i] = 0.f; b[i] = 0.f; }
}

// ---------------------------------------------------------------------------
// Persistent recurrence kernel: whole encoder + decoder GRU chain in one
// launch, grid-wide flag barrier between dependent phases.
// Grid: 128 CTAs x 256 threads. CTA c owns output columns j0 = c*4 .. c*4+3.
// Thread: b = tid>>2 (batch row), jj = tid&3 (column within tile).
// ---------------------------------------------------------------------------
__device__ __forceinline__ void gridbar(unsigned gen)
{
    __syncthreads();
    if (threadIdx.x == 0) {
        __threadfence();
        ((volatile unsigned*)g_flags)[blockIdx.x] = gen;
    }
    if (blockIdx.x == 0) {
        if (threadIdx.x < NCTA) {
            while (((volatile unsigned*)g_flags)[threadIdx.x] < gen) __nanosleep(20);
        }
        __syncthreads();
        if (threadIdx.x == 0) {
            __threadfence();
            *(volatile unsigned*)&g_relgen = gen;
        }
    }
    if (threadIdx.x == 0) {
        while (*(volatile unsigned*)&g_relgen < gen) __nanosleep(20);
    }
    __syncthreads();
}

__global__ __launch_bounds__(256, 1) void recurrence(
    const float* __restrict__ Wz, const float* __restrict__ Wr,
    const float* __restrict__ Wn,
    const float* __restrict__ bz, const float* __restrict__ br,
    const float* __restrict__ bn)
{
    __shared__ float smU[4][516];
    __shared__ float smZ[4][516];
    __shared__ float smR[4][516];
    __shared__ float smN[4][516];

    const int tid = threadIdx.x;
    const int c   = blockIdx.x;
    const int j0  = c * 4;

    // stage this CTA's weight rows once (constant across all timesteps)
#pragma unroll
    for (int q = 0; q < 2; q++) {
        int idx = tid + q * 256;          // float4 index, 0..511
        int row = idx >> 7;               // 0..3
        int col = (idx & 127) << 2;       // 0..508
        *(float4*)&smU[row][col] = *(const float4*)&g_Ut[(size_t)(j0 + row) * D + col];
        *(float4*)&smZ[row][col] = *(const float4*)&Wz[(size_t)(j0 + row) * D + col];
        *(float4*)&smR[row][col] = *(const float4*)&Wr[(size_t)(j0 + row) * D + col];
        *(float4*)&smN[row][col] = *(const float4*)&Wn[(size_t)(j0 + row) * D + col];
    }
    __syncthreads();

    const int b  = tid >> 2;
    const int jj = tid & 3;
    const int j  = j0 + jj;
    const int idx = b * D + j;
    const float bzv = bz[j], brv = br[j], bnv = bn[j];
    const float* uRow = smU[jj];
    const float* zRow = smZ[jj];
    const float* rRow = smR[jj];
    const float* nRow = smN[jj];

    unsigned gen = 0;

    // ---------------- encoder ----------------
    for (int t = 0; t < TSRC; t++) {
        const int cur = t & 1, nxt = cur ^ 1;

        // cell1: hW = h1 @ U ; gates from precomputed Genc
        {
            const float* hrow = g_h1 + cur * S + b * D;
            float a0 = 0.f, a1 = 0.f, a2 = 0.f, a3 = 0.f;
#pragma unroll 8
            for (int k = 0; k < D; k += 4) {
                float4 hv = ldcg4(hrow + k);
                float4 uv = *(const float4*)(uRow + k);
                a0 = fmaf(hv.x, uv.x, a0); a1 = fmaf(hv.y, uv.y, a1);
                a2 = fmaf(hv.z, uv.z, a2); a3 = fmaf(hv.w, uv.w, a3);
            }
            float hW = (a0 + a1) + (a2 + a3);
            const float* g = g_Genc + (size_t)(t * BB + b) * 1536;
            float z = 1.f / (1.f + __expf(-(g[j] + hW)));
            float r = 1.f / (1.f + __expf(-(g[512 + j] + hW)));
            float n = tanhf(g[1024 + j] + r * hW);
            float h = ldcg1(hrow + j);
            g_h1[nxt * S + idx] = (1.f - z) * h + z * n;
        }
        gridbar(++gen);

        // cell2: 4 dots — h2@U plus h1new@{Wz,Wr,Wn}; explicit biases
        {
            const float* h2row = g_h2 + cur * S + b * D;
            const float* h1row = g_h1 + nxt * S + b * D;
            float u0 = 0.f, u1 = 0.f, z0 = 0.f, z1 = 0.f;
            float r0 = 0.f, r1 = 0.f, n0 = 0.f, n1 = 0.f;
#pragma unroll 4
            for (int k = 0; k < D; k += 4) {
                float4 h2v = ldcg4(h2row + k);
                float4 h1v = ldcg4(h1row + k);
                float4 uv = *(const float4*)(uRow + k);
                float4 zv = *(const float4*)(zRow + k);
                float4 rv = *(const float4*)(rRow + k);
                float4 nv = *(const float4*)(nRow + k);
                u0 = fmaf(h2v.x, uv.x, u0); u1 = fmaf(h2v.y, uv.y, u1);
                u0 = fmaf(h2v.z, uv.z, u0); u1 = fmaf(h2v.w, uv.w, u1);
                z0 = fmaf(h1v.x, zv.x, z0); z1 = fmaf(h1v.y, zv.y, z1);
                z0 = fmaf(h1v.z, zv.z, z0); z1 = fmaf(h1v.w, zv.w, z1);
                r0 = fmaf(h1v.x, rv.x, r0); r1 = fmaf(h1v.y, rv.y, r1);
                r0 = fmaf(h1v.z, rv.z, r0); r1 = fmaf(h1v.w, rv.w, r1);
                n0 = fmaf(h1v.x, nv.x, n0); n1 = fmaf(h1v.y, nv.y, n1);
                n0 = fmaf(h1v.z, nv.z, n0); n1 = fmaf(h1v.w, nv.w, n1);
            }
            float dU = u0 + u1;
            float z = 1.f / (1.f + __expf(-(z0 + z1 + bzv + dU)));
            float r = 1.f / (1.f + __expf(-(r0 + r1 + brv + dU)));
            float n = tanhf(n0 + n1 + bnv + r * dU);
            float h = ldcg1(h2row + j);
            float hn = (1.f - z) * h + z * n;
            g_h2[nxt * S + idx] = hn;
            g_H[(size_t)t * S + idx] = hn;
        }
        gridbar(++gen);
    }

    // ---------------- decoder (attention deferred — not in the chain) -------
    for (int t = 0; t < TTGT; t++) {
        const int cur = t & 1, nxt = cur ^ 1;
        const float* hrow = g_h2 + cur * S + b * D;
        float a0 = 0.f, a1 = 0.f, a2 = 0.f, a3 = 0.f;
#pragma unroll 8
        for (int k = 0; k < D; k += 4) {
            float4 hv = ldcg4(hrow + k);
            float4 uv = *(const float4*)(uRow + k);
            a0 = fmaf(hv.x, uv.x, a0); a1 = fmaf(hv.y, uv.y, a1);
            a2 = fmaf(hv.z, uv.z, a2); a3 = fmaf(hv.w, uv.w, a3);
        }
        float hW = (a0 + a1) + (a2 + a3);
        const float* g = g_Gdec + (size_t)(t * BB + b) * 1536;
        float z = 1.f / (1.f + __expf(-(g[j] + hW)));
        float r = 1.f / (1.f + __expf(-(g[512 + j] + hW)));
        float n = tanhf(g[1024 + j] + r * hW);
        float h = ldcg1(hrow + j);
        float hn = (1.f - z) * h + z * n;
        g_h2[nxt * S + idx] = hn;
        g_hall[(size_t)t * S + idx] = hn;
        gridbar(++gen);
    }

    // reset barrier state for the next invocation (all CTAs are past the
    // final barrier, so no one reads these again this run)
    if (blockIdx.x == 0) {
        if (tid < NCTA) ((volatile unsigned*)g_flags)[tid] = 0;
        if (tid == 0) *(volatile unsigned*)&g_relgen = 0;
    }
}

// ---------------------------------------------------------------------------
// Batched attention: one block per batch row, all 48 decoder steps at once.
// scores[i][j] = hall[i,b]·H[j,b] * scale (masked) -> softmax -> ctx.
// ---------------------------------------------------------------------------
__global__ __launch_bounds__(256) void attn_batched(
    const int* __restrict__ src, float* __restrict__ ctx)
{
    const int b = blockIdx.x;
    const int tid = threadIdx.x;
    __shared__ float Hs[48][68];
    __shared__ float Qs[48][68];
    __shared__ float Sc[48][49];
    __shared__ float maskv[48];

    if (tid < TSRC) maskv[tid] = (src[tid * BB + b] == 0) ? 1.f : 0.f;

    const int ti = tid >> 4;   // 0..15 -> rows 3ti..3ti+2 (tgt)
    const int tj = tid & 15;   // 0..15 -> cols 3tj..3tj+2 (src)
    float acc[3][3] = {};

    for (int kc = 0; kc < 8; kc++) {
#pragma unroll
        for (int q = 0; q < 3; q++) {
            int idx = tid + q * 256;        // 0..767
            int row = idx >> 4;             // 0..47
            int col = (idx & 15) * 4;       // 0..60
            *(float4*)&Hs[row][col] =
                *(const float4*)&g_H[(size_t)row * S + b * D + kc * 64 + col];
            *(float4*)&Qs[row][col] =
                *(const float4*)&g_hall[(size_t)row * S + b * D + kc * 64 + col];
        }
        __syncthreads();
#pragma unroll 4
        for (int k = 0; k < 64; k += 4) {
            float4 q0 = *(const float4*)&Qs[3 * ti + 0][k];
            float4 q1 = *(const float4*)&Qs[3 * ti + 1][k];
            float4 q2 = *(const float4*)&Qs[3 * ti + 2][k];
            float4 h0 = *(const float4*)&Hs[3 * tj + 0][k];
            float4 h1 = *(const float4*)&Hs[3 * tj + 1][k];
            float4 h2 = *(const float4*)&Hs[3 * tj + 2][k];
#define DOT4A(A, B, Cv) \
            Cv = fmaf(A.x, B.x, Cv); Cv = fmaf(A.y, B.y, Cv); \
            Cv = fmaf(A.z, B.z, Cv); Cv = fmaf(A.w, B.w, Cv);
            DOT4A(q0, h0, acc[0][0]) DOT4A(q0, h1, acc[0][1]) DOT4A(q0, h2, acc[0][2])
            DOT4A(q1, h0, acc[1][0]) DOT4A(q1, h1, acc[1][1]) DOT4A(q1, h2, acc[1][2])
            DOT4A(q2, h0, acc[2][0]) DOT4A(q2, h1, acc[2][1]) DOT4A(q2, h2, acc[2][2])
#undef DOT4A
        }
        __syncthreads();
    }
#pragma unroll
    for (int i = 0; i < 3; i++)
#pragma unroll
        for (int jq = 0; jq < 3; jq++)
            Sc[3 * ti + i][3 * tj + jq] = acc[i][jq];
    __syncthreads();

    // mask + softmax per target row
    if (tid < TTGT) {
        const float scale = 0.044194173824159216f;  // 1/sqrt(512)
        float m = -1e30f;
        float sv[48];
#pragma unroll 8
        for (int jq = 0; jq < TSRC; jq++) {
            float s = (maskv[jq] != 0.f) ? -1e9f : Sc[tid][jq] * scale;
            sv[jq] = s;
            m = fmaxf(m, s);
        }
        float ssum = 0.f;
#pragma unroll 8
        for (int jq = 0; jq < TSRC; jq++) {
            float e = __expf(sv[jq] - m);
            sv[jq] = e;
            ssum += e;
        }
        float inv = 1.f / ssum;
#pragma unroll 8
        for (int jq = 0; jq < TSRC; jq++) Sc[tid][jq] = sv[jq] * inv;
    }
    __syncthreads();

    // ctx[i][:] = sum_j alpha[i][j] * H[j][:]
    for (int kc = 0; kc < 8; kc++) {
#pragma unroll
        for (int q = 0; q < 3; q++) {
            int idx = tid + q * 256;
            int row = idx >> 4;
            int col = (idx & 15) * 4;
            *(float4*)&Hs[row][col] =
                *(const float4*)&g_H[(size_t)row * S + b * D + kc * 64 + col];
        }
        __syncthreads();
#pragma unroll
        for (int q = 0; q < 3; q++) {
            int idx = tid + q * 256;
            int i = idx >> 4;
            int d4 = (idx & 15) * 4;
            float4 cv = make_float4(0.f, 0.f, 0.f, 0.f);
#pragma unroll 8
            for (int jq = 0; jq < TSRC; jq++) {
                float a = Sc[i][jq];
                float4 hv = *(const float4*)&Hs[jq][d4];
                cv.x = fmaf(a, hv.x, cv.x); cv.y = fmaf(a, hv.y, cv.y);
                cv.z = fmaf(a, hv.z, cv.z); cv.w = fmaf(a, hv.w, cv.w);
            }
            *(float4*)&ctx[(size_t)i * S + b * D + kc * 64 + d4] = cv;
        }
        __syncthreads();
    }
}

// ---------------------------------------------------------------------------
extern "C" void kernel_launch(void* const* d_in, const int* in_sizes, int n_in,
                              void* d_out, int out_size)
{
    const int*   src  = (const int*)d_in[0];
    const int*   tgt  = (const int*)d_in[1];
    const float* U    = (const float*)d_in[2];
    const float* Wz   = (const float*)d_in[3];
    const float* bz   = (const float*)d_in[4];
    const float* Wr   = (const float*)d_in[5];
    const float* br   = (const float*)d_in[6];
    const float* Wn   = (const float*)d_in[7];
    const float* bn   = (const float*)d_in[8];
    const float* Een  = (const float*)d_in[9];
    const float* Ede  = (const float*)d_in[10];
    const float* Wout = (const float*)d_in[11];
    const float* Wctx = (const float*)d_in[12];
    float* out = (float*)d_out;

    float *pWcat, *pbcat, *pUt, *pGenc, *pGdec, *ph1, *ph2, *pctx, *phall, *pout;
    cudaGetSymbolAddress((void**)&pWcat, g_Wcat);
    cudaGetSymbolAddress((void**)&pbcat, g_bcat);
    cudaGetSymbolAddress((void**)&pUt,   g_Ut);
    cudaGetSymbolAddress((void**)&pGenc, g_Genc);
    cudaGetSymbolAddress((void**)&pGdec, g_Gdec);
    cudaGetSymbolAddress((void**)&ph1,   g_h1);
    cudaGetSymbolAddress((void**)&ph2,   g_h2);
    cudaGetSymbolAddress((void**)&pctx,  g_ctx);
    cudaGetSymbolAddress((void**)&phall, g_hall);
    cudaGetSymbolAddress((void**)&pout,  g_out);

    // launches 1-5: setup + gate precompute (parallel work)
    build_wcat<<<(1536 * D + 255) / 256, 256>>>(Wz, bz, Wr, br, Wn, bn);
    transpose512<<<dim3(16, 16), dim3(32, 8)>>>(U, pUt);
    zero2<<<(S + 255) / 256, 256>>>(ph1, ph2, S);
    sgemm_tf32<<<dim3(12, 24), 256>>>(nullptr, src, Een, pWcat, pbcat, nullptr,
                                      pGenc, M3, 1536, D);
    sgemm_tf32<<<dim3(12, 24), 256>>>(nullptr, tgt, Ede, pWcat, pbcat, nullptr,
                                      pGdec, M3, 1536, D);

    // launch 6 (ncu -s 5 lands here): the whole sequential chain
    recurrence<<<NCTA, 256>>>(Wz, Wr, Wn, bz, br, bn);

    // launch 7: all 48 attention steps, batched
    attn_batched<<<BB, 256>>>(src, pctx);

    // launches 8-9: deferred output projection + big logits GEMM (tf32)
    sgemm_tf32<<<dim3(4, 24), 256>>>(pctx, nullptr, nullptr, Wctx, nullptr, phall,
                                     pout, M3, D, D);
    sgemm_tf32<<<dim3(250, 24), 256>>>(pout, nullptr, nullptr, Wout, nullptr, nullptr,
                                       out, M3, VDE, D);
}

// round 5
// speedup vs baseline: 1.2739x; 1.2739x over previous
#include <cuda_runtime.h>
#include <math.h>

// Problem constants
#define D    512
#define BB   64
#define TSRC 48
#define TTGT 48
#define VDE  32000
#define S    (BB * D)        // 32768 = one (B,D) state
#define M3   (TSRC * BB)     // 3072 rows

// recurrence partition: 4 b-groups x 32 j-groups = 128 CTAs
#define NGB 4
#define NGJ 32
#define NB  16               // batch rows per CTA
#define NJ  16               // output columns per CTA
#define RSTR 516             // smem row stride (floats); 516/4=129 odd -> conflict-free
#define RS  (NB * RSTR)      // floats per smem region

// ---------------- scratch (device globals; no allocation allowed) ------------
__device__ float g_Wcat[1536 * D];
__device__ float g_bcat[1536];
__device__ float g_Ut[D * D];            // U transposed: Ut[j][k] = U[k][j]
__device__ float g_Genc[M3 * 1536];
__device__ float g_Gdec[M3 * 1536];
__device__ float g_h1[2 * S];
__device__ float g_h2[2 * S];
__device__ float g_H[TSRC * S];
__device__ float g_hall[TTGT * S];
__device__ float g_ctx[TTGT * S];
__device__ float g_out[TTGT * S];
__device__ float g_Wout32[VDE * D];      // tf32-rounded copy of W_out
__device__ unsigned g_flags[NGB * NGJ];  // per-group barrier flags

// ---------------------------------------------------------------------------
__device__ __forceinline__ float4 ldcg4(const float* p) {
    float4 v;
    asm volatile("ld.global.cg.v4.f32 {%0,%1,%2,%3}, [%4];"
                 : "=f"(v.x), "=f"(v.y), "=f"(v.z), "=f"(v.w) : "l"(p));
    return v;
}

__device__ __forceinline__ unsigned f2tf32(float x) {
    unsigned r;
    asm("cvt.rna.tf32.f32 %0, %1;" : "=r"(r) : "f"(x));
    return r;
}

__device__ __forceinline__ void cpasync16(void* sptr, const void* gptr) {
    unsigned s = (unsigned)__cvta_generic_to_shared(sptr);
    asm volatile("cp.async.ca.shared.global [%0], [%1], 16;" :: "r"(s), "l"(gptr));
}

// ---------------------------------------------------------------------------
// Generic tf32 NT GEMM (round-3 kernel) for gate precompute + out-projection.
// cvtout: round C values to tf32 on writeback (feeds the logits GEMM).
// ---------------------------------------------------------------------------
__global__ __launch_bounds__(256) void sgemm_tf32(
    const float* __restrict__ A, const int* __restrict__ ids,
    const float* __restrict__ E, const float* __restrict__ Bm,
    const float* __restrict__ bias, const float* __restrict__ addend,
    float* __restrict__ C, int M, int N, int K, int cvtout)
{
    __shared__ unsigned As[128 * 36];
    __shared__ unsigned Bs[128 * 36];

    const int tid  = threadIdx.x;
    const int lane = tid & 31;
    const int warp = tid >> 5;
    const int row0 = blockIdx.y * 128;
    const int col0 = blockIdx.x * 128;

    const int mwarp = (warp >> 2) * 64;
    const int nwarp = (warp & 3) * 32;
    const int gid = lane >> 2;
    const int tig = lane & 3;

    const int lr = tid >> 3;
    const int lc = (tid & 7) * 4;

    const float* aPtr[4];
    const float* bPtr[4];
#pragma unroll
    for (int i = 0; i < 4; i++) {
        int r = row0 + lr + 32 * i;
        aPtr[i] = ids ? (E + (size_t)ids[r] * K) : (A + (size_t)r * K);
        bPtr[i] = Bm + (size_t)(col0 + lr + 32 * i) * K;
    }

    float acc[4][4][4];
#pragma unroll
    for (int mt = 0; mt < 4; mt++)
#pragma unroll
        for (int nt = 0; nt < 4; nt++)
#pragma unroll
            for (int q = 0; q < 4; q++) acc[mt][nt][q] = 0.f;

    const int kchunks = K >> 5;
    float4 aReg[4], bReg[4];
#pragma unroll
    for (int i = 0; i < 4; i++) {
        aReg[i] = *(const float4*)(aPtr[i] + lc);
        bReg[i] = *(const float4*)(bPtr[i] + lc);
    }

    for (int ch = 0; ch < kchunks; ch++) {
#pragma unroll
        for (int i = 0; i < 4; i++) {
            int base = (lr + 32 * i) * 36 + lc;
            uint4 av, bv;
            av.x = f2tf32(aReg[i].x); av.y = f2tf32(aReg[i].y);
            av.z = f2tf32(aReg[i].z); av.w = f2tf32(aReg[i].w);
            bv.x = f2tf32(bReg[i].x); bv.y = f2tf32(bReg[i].y);
            bv.z = f2tf32(bReg[i].z); bv.w = f2tf32(bReg[i].w);
            *(uint4*)&As[base] = av;
            *(uint4*)&Bs[base] = bv;
        }
        __syncthreads();

        if (ch + 1 < kchunks) {
            int koff = (ch + 1) * 32 + lc;
#pragma unroll
            for (int i = 0; i < 4; i++) {
                aReg[i] = *(const float4*)(aPtr[i] + koff);
                bReg[i] = *(const float4*)(bPtr[i] + koff);
            }
        }

#pragma unroll
        for (int ks = 0; ks < 4; ks++) {
            int k0 = ks * 8;
            unsigned bf[4][2];
#pragma unroll
            for (int nt = 0; nt < 4; nt++) {
                int nb = nwarp + nt * 8 + gid;
                bf[nt][0] = Bs[nb * 36 + k0 + tig];
                bf[nt][1] = Bs[nb * 36 + k0 + tig + 4];
            }
#pragma unroll
            for (int mt = 0; mt < 4; mt++) {
                int rm = mwarp + mt * 16 + gid;
                unsigned a0 = As[rm * 36 + k0 + tig];
                unsigned a1 = As[(rm + 8) * 36 + k0 + tig];
                unsigned a2 = As[rm * 36 + k0 + tig + 4];
                unsigned a3 = As[(rm + 8) * 36 + k0 + tig + 4];
#pragma unroll
                for (int nt = 0; nt < 4; nt++) {
                    asm volatile(
                        "mma.sync.aligned.m16n8k8.row.col.f32.tf32.tf32.f32 "
                        "{%0,%1,%2,%3}, {%4,%5,%6,%7}, {%8,%9}, {%0,%1,%2,%3};"
                        : "+f"(acc[mt][nt][0]), "+f"(acc[mt][nt][1]),
                          "+f"(acc[mt][nt][2]), "+f"(acc[mt][nt][3])
                        : "r"(a0), "r"(a1), "r"(a2), "r"(a3),
                          "r"(bf[nt][0]), "r"(bf[nt][1]));
                }
            }
        }
        __syncthreads();
    }

#pragma unroll
    for (int mt = 0; mt < 4; mt++) {
        int r = row0 + mwarp + mt * 16 + gid;
#pragma unroll
        for (int nt = 0; nt < 4; nt++) {
            int c = col0 + nwarp + nt * 8 + tig * 2;
            float v0 = acc[mt][nt][0], v1 = acc[mt][nt][1];
            float v2 = acc[mt][nt][2], v3 = acc[mt][nt][3];
            if (bias) {
                float b0 = bias[c], b1 = bias[c + 1];
                v0 += b0; v1 += b1; v2 += b0; v3 += b1;
            }
            if (addend) {
                float2 a0 = *(const float2*)&addend[(size_t)r * N + c];
                float2 a1 = *(const float2*)&addend[(size_t)(r + 8) * N + c];
                v0 += a0.x; v1 += a0.y; v2 += a1.x; v3 += a1.y;
            }
            if (cvtout) {
                v0 = __uint_as_float(f2tf32(v0)); v1 = __uint_as_float(f2tf32(v1));
                v2 = __uint_as_float(f2tf32(v2)); v3 = __uint_as_float(f2tf32(v3));
            }
            float2 o0; o0.x = v0; o0.y = v1;
            float2 o1; o1.x = v2; o1.y = v3;
            *(float2*)&C[(size_t)r * N + c] = o0;
            *(float2*)&C[(size_t)(r + 8) * N + c] = o1;
        }
    }
}

// ---------------------------------------------------------------------------
// Dedicated logits GEMM: C[3072,32000] = A[3072,512] @ B[32000,512]^T.
// Inputs pre-rounded to tf32. BM=256, BN=128, BK=16, 512 threads,
// 2-stage cp.async pipeline, XOR-swizzled 48KB smem (exactly at static limit).
// ---------------------------------------------------------------------------
#define LNCH 32   // 512/16 k-chunks

__device__ __forceinline__ int swidx(int r, int k) {
    return r * 16 + ((((k) >> 2) ^ ((r >> 1) & 3)) << 2) + (k & 3);
}

__global__ __launch_bounds__(512) void gemm_logits(
    const float* __restrict__ A, const float* __restrict__ B,
    float* __restrict__ C)
{
    __shared__ float4 sA[2][256 * 4];
    __shared__ float4 sB[2][128 * 4];

    const int tid  = threadIdx.x;
    const int lane = tid & 31;
    const int warp = tid >> 5;
    const int row0 = blockIdx.y * 256;
    const int col0 = blockIdx.x * 128;

    const int mwarp = (warp >> 2) * 64;   // 4 warp-rows
    const int nwarp = (warp & 3) * 32;    // 4 warp-cols
    const int gid = lane >> 2;
    const int tig = lane & 3;

    // cp.async mapping
    const int ra = tid >> 2;              // 0..127 (and +128)
    const int ga = tid & 3;
    const float* gA0 = A + (size_t)(row0 + ra) * D;
    const float* gA1 = A + (size_t)(row0 + ra + 128) * D;
    const float* gB0 = B + (size_t)(col0 + ra) * D;
    float4* dA0 = &sA[0][ra * 4 + (ga ^ ((ra >> 1) & 3))];
    float4* dA1 = &sA[0][(ra + 128) * 4 + (ga ^ (((ra + 128) >> 1) & 3))];
    float4* dB0 = &sB[0][ra * 4 + (ga ^ ((ra >> 1) & 3))];
    const int stg = 256 * 4;              // float4 stride between stages
    const int stgB = 128 * 4;

#define ISSUE(ch, buf)                                                      \
    do {                                                                    \
        int ko = (ch) * 16 + ga * 4;                                        \
        cpasync16(dA0 + (buf) * stg,  gA0 + ko);                            \
        cpasync16(dA1 + (buf) * stg,  gA1 + ko);                            \
        cpasync16(dB0 + (buf) * stgB, gB0 + ko);                            \
        asm volatile("cp.async.commit_group;");                            \
    } while (0)

    float acc[4][4][4];
#pragma unroll
    for (int mt = 0; mt < 4; mt++)
#pragma unroll
        for (int nt = 0; nt < 4; nt++)
#pragma unroll
            for (int q = 0; q < 4; q++) acc[mt][nt][q] = 0.f;

    ISSUE(0, 0);
    ISSUE(1, 1);

    for (int ch = 0; ch < LNCH; ch++) {
        if (ch == LNCH - 1) asm volatile("cp.async.wait_group 0;");
        else                asm volatile("cp.async.wait_group 1;");
        __syncthreads();

        const float* Af = (const float*)&sA[ch & 1][0];
        const float* Bf = (const float*)&sB[ch & 1][0];
#pragma unroll
        for (int ks = 0; ks < 2; ks++) {
            int k0 = ks * 8;
            unsigned bf[4][2];
#pragma unroll
            for (int nt = 0; nt < 4; nt++) {
                int nb = nwarp + nt * 8 + gid;
                bf[nt][0] = __float_as_uint(Bf[swidx(nb, k0 + tig)]);
                bf[nt][1] = __float_as_uint(Bf[swidx(nb, k0 + tig + 4)]);
            }
#pragma unroll
            for (int mt = 0; mt < 4; mt++) {
                int rm = mwarp + mt * 16 + gid;
                unsigned a0 = __float_as_uint(Af[swidx(rm, k0 + tig)]);
                unsigned a1 = __float_as_uint(Af[swidx(rm + 8, k0 + tig)]);
                unsigned a2 = __float_as_uint(Af[swidx(rm, k0 + tig + 4)]);
                unsigned a3 = __float_as_uint(Af[swidx(rm + 8, k0 + tig + 4)]);
#pragma unroll
                for (int nt = 0; nt < 4; nt++) {
                    asm volatile(
                        "mma.sync.aligned.m16n8k8.row.col.f32.tf32.tf32.f32 "
                        "{%0,%1,%2,%3}, {%4,%5,%6,%7}, {%8,%9}, {%0,%1,%2,%3};"
                        : "+f"(acc[mt][nt][0]), "+f"(acc[mt][nt][1]),
                          "+f"(acc[mt][nt][2]), "+f"(acc[mt][nt][3])
                        : "r"(a0), "r"(a1), "r"(a2), "r"(a3),
                          "r"(bf[nt][0]), "r"(bf[nt][1]));
                }
            }
        }
        __syncthreads();
        if (ch + 2 < LNCH) ISSUE(ch + 2, ch & 1);
    }
#undef ISSUE

#pragma unroll
    for (int mt = 0; mt < 4; mt++) {
        size_t r = (size_t)(row0 + mwarp + mt * 16 + gid);
#pragma unroll
        for (int nt = 0; nt < 4; nt++) {
            int c = col0 + nwarp + nt * 8 + tig * 2;
            float2 o0; o0.x = acc[mt][nt][0]; o0.y = acc[mt][nt][1];
            float2 o1; o1.x = acc[mt][nt][2]; o1.y = acc[mt][nt][3];
            *(float2*)&C[r * VDE + c] = o0;
            *(float2*)&C[(r + 8) * VDE + c] = o1;
        }
    }
}

// ---------------------------------------------------------------------------
__global__ void build_wcat(const float* __restrict__ Wz, const float* __restrict__ bz,
                           const float* __restrict__ Wr, const float* __restrict__ br,
                           const float* __restrict__ Wn, const float* __restrict__ bn)
{
    int idx = blockIdx.x * blockDim.x + threadIdx.x;
    if (idx >= 1536 * D) return;
    int j = idx / D, k = idx % D;
    int g = j >> 9, jr = j & 511;
    const float* W = (g == 0) ? Wz : (g == 1) ? Wr : Wn;
    g_Wcat[idx] = W[jr * D + k];
    if (k == 0) {
        const float* bvec = (g == 0) ? bz : (g == 1) ? br : bn;
        g_bcat[j] = bvec[jr];
    }
}

__global__ void transpose512(const float* __restrict__ U, float* __restrict__ Ut)
{
    __shared__ float tile[32][33];
    int k0 = blockIdx.y * 32;
    int j0 = blockIdx.x * 32;
    int tx = threadIdx.x, ty = threadIdx.y;
#pragma unroll
    for (int i = 0; i < 4; i++)
        tile[ty + i * 8][tx] = U[(size_t)(k0 + ty + i * 8) * D + j0 + tx];
    __syncthreads();
#pragma unroll
    for (int i = 0; i < 4; i++)
        Ut[(size_t)(j0 + ty + i * 8) * D + k0 + tx] = tile[tx][ty + i * 8];
}

__global__ void zero2(float* a, float* b, int n, unsigned* flags)
{
    int i = blockIdx.x * blockDim.x + threadIdx.x;
    if (i < n) { a[i] = 0.f; b[i] = 0.f; }
    if (i < NGB * NGJ) flags[i] = 0u;
}

// round W_out to tf32 once (removes per-tile cvt from the logits GEMM)
__global__ void cvt_wout(const float* __restrict__ W, float* __restrict__ Wt)
{
    int i = blockIdx.x * blockDim.x + threadIdx.x;   // float4 index
    float4 v = *(const float4*)(W + (size_t)i * 4);
    uint4 o;
    o.x = f2tf32(v.x); o.y = f2tf32(v.y); o.z = f2tf32(v.z); o.w = f2tf32(v.w);
    *(uint4*)(Wt + (size_t)i * 4) = o;
}

// ---------------------------------------------------------------------------
// Persistent recurrence: 128 CTAs = 4 b-groups x 32 j-groups.
// CTA owns 16 batch rows x 16 output columns. Weights for its 16 columns live
// in smem; the 16 h-rows are staged into smem per dot. Barriers sync only the
// 32 CTAs of one b-group (all-poll-all on 32 flags).
// ---------------------------------------------------------------------------
__device__ __forceinline__ void groupbar(volatile unsigned* gf, int gj, unsigned gen)
{
    __syncthreads();
    if (threadIdx.x == 0) {
        __threadfence();
        gf[gj] = gen;
    }
    if (threadIdx.x < NGJ) {
        while (gf[threadIdx.x] < gen) __nanosleep(32);
    }
    __syncthreads();
}

__device__ __forceinline__ void stageH(float* dst, const float* src)
{
#pragma unroll
    for (int q = 0; q < 8; q++) {
        int idx = threadIdx.x + q * 256;      // float4 units, 0..2047
        int row = idx >> 7;                   // 0..15
        int col = (idx & 127) << 2;           // 0..508
        float4 v = ldcg4(src + row * D + col);
        *(float4*)&dst[row * RSTR + col] = v;
    }
}

__global__ __launch_bounds__(256, 1) void recurrence(
    const float* __restrict__ Wz, const float* __restrict__ Wr,
    const float* __restrict__ Wn,
    const float* __restrict__ bz, const float* __restrict__ br,
    const float* __restrict__ bn)
{
    extern __shared__ float sm[];
    float* sWU = sm;
    float* sWZ = sm + RS;
    float* sWR = sm + 2 * RS;
    float* sWN = sm + 3 * RS;
    float* sH1 = sm + 4 * RS;
    float* sH2 = sm + 5 * RS;

    const int tid = threadIdx.x;
    const int gb  = blockIdx.x & 3;
    const int gj  = blockIdx.x >> 2;
    const int b0  = gb * NB;
    const int j0  = gj * NJ;
    const int jl  = tid >> 4;
    const int bl  = tid & 15;
    const int b   = b0 + bl;
    const int j   = j0 + jl;
    volatile unsigned* gf = (volatile unsigned*)(g_flags + gb * NGJ);

    // stage this CTA's weight rows (constant over all steps)
#pragma unroll
    for (int q = 0; q < 8; q++) {
        int idx = tid + q * 256;
        int row = idx >> 7;
        int col = (idx & 127) << 2;
        *(float4*)&sWU[row * RSTR + col] = *(const float4*)&g_Ut[(size_t)(j0 + row) * D + col];
        *(float4*)&sWZ[row * RSTR + col] = *(const float4*)&Wz[(size_t)(j0 + row) * D + col];
        *(float4*)&sWR[row * RSTR + col] = *(const float4*)&Wr[(size_t)(j0 + row) * D + col];
        *(float4*)&sWN[row * RSTR + col] = *(const float4*)&Wn[(size_t)(j0 + row) * D + col];
    }
    const float bzv = bz[j], brv = br[j], bnv = bn[j];
    const float* wu = &sWU[jl * RSTR];
    const float* wz = &sWZ[jl * RSTR];
    const float* wr = &sWR[jl * RSTR];
    const float* wn = &sWN[jl * RSTR];
    const float* h1r = &sH1[bl * RSTR];
    const float* h2r = &sH2[bl * RSTR];

    __syncthreads();
    stageH(sH1, g_h1 + 0 * S + b0 * D);   // initial h1 (zeros)
    __syncthreads();

    unsigned gen = 0;

    // ---------------- encoder ----------------
    for (int t = 0; t < TSRC; t++) {
        const int cur = t & 1, nxt = cur ^ 1;

        // cell1: sH1 holds h1[cur]
        {
            float a0 = 0.f, a1 = 0.f, a2 = 0.f, a3 = 0.f;
#pragma unroll 8
            for (int k = 0; k < D; k += 4) {
                float4 hv = *(const float4*)&h1r[k];
                float4 wv = *(const float4*)&wu[k];
                a0 = fmaf(hv.x, wv.x, a0); a1 = fmaf(hv.y, wv.y, a1);
                a2 = fmaf(hv.z, wv.z, a2); a3 = fmaf(hv.w, wv.w, a3);
            }
            float hW = (a0 + a1) + (a2 + a3);
            const float* g = g_Genc + (size_t)(t * BB + b) * 1536;
            float z = 1.f / (1.f + __expf(-(g[j] + hW)));
            float r = 1.f / (1.f + __expf(-(g[512 + j] + hW)));
            float n = tanhf(g[1024 + j] + r * hW);
            float h = h1r[j];
            g_h1[(size_t)nxt * S + b * D + j] = (1.f - z) * h + z * n;
        }
        groupbar(gf, gj, ++gen);

        // cell2: stage h2[cur] and h1[nxt]
        stageH(sH2, g_h2 + (size_t)cur * S + b0 * D);
        stageH(sH1, g_h1 + (size_t)nxt * S + b0 * D);
        __syncthreads();
        {
            float u0 = 0.f, u1 = 0.f, z0 = 0.f, z1 = 0.f;
            float r0 = 0.f, r1 = 0.f, n0 = 0.f, n1 = 0.f;
#pragma unroll 4
            for (int k = 0; k < D; k += 4) {
                float4 h2v = *(const float4*)&h2r[k];
                float4 h1v = *(const float4*)&h1r[k];
                float4 uv = *(const float4*)&wu[k];
                float4 zv = *(const float4*)&wz[k];
                float4 rv = *(const float4*)&wr[k];
                float4 nv = *(const float4*)&wn[k];
                u0 = fmaf(h2v.x, uv.x, u0); u1 = fmaf(h2v.y, uv.y, u1);
                u0 = fmaf(h2v.z, uv.z, u0); u1 = fmaf(h2v.w, uv.w, u1);
                z0 = fmaf(h1v.x, zv.x, z0); z1 = fmaf(h1v.y, zv.y, z1);
                z0 = fmaf(h1v.z, zv.z, z0); z1 = fmaf(h1v.w, zv.w, z1);
                r0 = fmaf(h1v.x, rv.x, r0); r1 = fmaf(h1v.y, rv.y, r1);
                r0 = fmaf(h1v.z, rv.z, r0); r1 = fmaf(h1v.w, rv.w, r1);
                n0 = fmaf(h1v.x, nv.x, n0); n1 = fmaf(h1v.y, nv.y, n1);
                n0 = fmaf(h1v.z, nv.z, n0); n1 = fmaf(h1v.w, nv.w, n1);
            }
            float dU = u0 + u1;
            float z = 1.f / (1.f + __expf(-(z0 + z1 + bzv + dU)));
            float r = 1.f / (1.f + __expf(-(r0 + r1 + brv + dU)));
            float n = tanhf(n0 + n1 + bnv + r * dU);
            float h = h2r[j];
            float hn = (1.f - z) * h + z * n;
            g_h2[(size_t)nxt * S + b * D + j] = hn;
            g_H[(size_t)t * S + b * D + j] = hn;
        }
        groupbar(gf, gj, ++gen);
        // next cell1 reads h1[nxt], which sH1 already holds
    }

    // ---------------- decoder (attention deferred) ----------------
    for (int t = 0; t < TTGT; t++) {
        const int cur = t & 1, nxt = cur ^ 1;
        stageH(sH2, g_h2 + (size_t)cur * S + b0 * D);
        __syncthreads();
        float a0 = 0.f, a1 = 0.f, a2 = 0.f, a3 = 0.f;
#pragma unroll 8
        for (int k = 0; k < D; k += 4) {
            float4 hv = *(const float4*)&h2r[k];
            float4 wv = *(const float4*)&wu[k];
            a0 = fmaf(hv.x, wv.x, a0); a1 = fmaf(hv.y, wv.y, a1);
            a2 = fmaf(hv.z, wv.z, a2); a3 = fmaf(hv.w, wv.w, a3);
        }
        float hW = (a0 + a1) + (a2 + a3);
        const float* g = g_Gdec + (size_t)(t * BB + b) * 1536;
        float z = 1.f / (1.f + __expf(-(g[j] + hW)));
        float r = 1.f / (1.f + __expf(-(g[512 + j] + hW)));
        float n = tanhf(g[1024 + j] + r * hW);
        float h = h2r[j];
        float hn = (1.f - z) * h + z * n;
        g_h2[(size_t)nxt * S + b * D + j] = hn;
        g_hall[(size_t)t * S + b * D + j] = hn;
        if (t < TTGT - 1) groupbar(gf, gj, ++gen);
    }
}

// ---------------------------------------------------------------------------
// Batched attention (round-4 kernel, unchanged — it worked)
// ---------------------------------------------------------------------------
__global__ __launch_bounds__(256) void attn_batched(
    const int* __restrict__ src, float* __restrict__ ctx)
{
    const int b = blockIdx.x;
    const int tid = threadIdx.x;
    __shared__ float Hs[48][68];
    __shared__ float Qs[48][68];
    __shared__ float Sc[48][49];
    __shared__ float maskv[48];

    if (tid < TSRC) maskv[tid] = (src[tid * BB + b] == 0) ? 1.f : 0.f;

    const int ti = tid >> 4;
    const int tj = tid & 15;
    float acc[3][3] = {};

    for (int kc = 0; kc < 8; kc++) {
#pragma unroll
        for (int q = 0; q < 3; q++) {
            int idx = tid + q * 256;
            int row = idx >> 4;
            int col = (idx & 15) * 4;
            *(float4*)&Hs[row][col] =
                *(const float4*)&g_H[(size_t)row * S + b * D + kc * 64 + col];
            *(float4*)&Qs[row][col] =
                *(const float4*)&g_hall[(size_t)row * S + b * D + kc * 64 + col];
        }
        __syncthreads();
#pragma unroll 4
        for (int k = 0; k < 64; k += 4) {
            float4 q0 = *(const float4*)&Qs[3 * ti + 0][k];
            float4 q1 = *(const float4*)&Qs[3 * ti + 1][k];
            float4 q2 = *(const float4*)&Qs[3 * ti + 2][k];
            float4 h0 = *(const float4*)&Hs[3 * tj + 0][k];
            float4 h1 = *(const float4*)&Hs[3 * tj + 1][k];
            float4 h2 = *(const float4*)&Hs[3 * tj + 2][k];
#define DOT4A(A, B, Cv) \
            Cv = fmaf(A.x, B.x, Cv); Cv = fmaf(A.y, B.y, Cv); \
            Cv = fmaf(A.z, B.z, Cv); Cv = fmaf(A.w, B.w, Cv);
            DOT4A(q0, h0, acc[0][0]) DOT4A(q0, h1, acc[0][1]) DOT4A(q0, h2, acc[0][2])
            DOT4A(q1, h0, acc[1][0]) DOT4A(q1, h1, acc[1][1]) DOT4A(q1, h2, acc[1][2])
            DOT4A(q2, h0, acc[2][0]) DOT4A(q2, h1, acc[2][1]) DOT4A(q2, h2, acc[2][2])
#undef DOT4A
        }
        __syncthreads();
    }
#pragma unroll
    for (int i = 0; i < 3; i++)
#pragma unroll
        for (int jq = 0; jq < 3; jq++)
            Sc[3 * ti + i][3 * tj + jq] = acc[i][jq];
    __syncthreads();

    if (tid < TTGT) {
        const float scale = 0.044194173824159216f;
        float m = -1e30f;
        float sv[48];
#pragma unroll 8
        for (int jq = 0; jq < TSRC; jq++) {
            float s = (maskv[jq] != 0.f) ? -1e9f : Sc[tid][jq] * scale;
            sv[jq] = s;
            m = fmaxf(m, s);
        }
        float ssum = 0.f;
#pragma unroll 8
        for (int jq = 0; jq < TSRC; jq++) {
            float e = __expf(sv[jq] - m);
            sv[jq] = e;
            ssum += e;
        }
        float inv = 1.f / ssum;
#pragma unroll 8
        for (int jq = 0; jq < TSRC; jq++) Sc[tid][jq] = sv[jq] * inv;
    }
    __syncthreads();

    for (int kc = 0; kc < 8; kc++) {
#pragma unroll
        for (int q = 0; q < 3; q++) {
            int idx = tid + q * 256;
            int row = idx >> 4;
            int col = (idx & 15) * 4;
            *(float4*)&Hs[row][col] =
                *(const float4*)&g_H[(size_t)row * S + b * D + kc * 64 + col];
        }
        __syncthreads();
#pragma unroll
        for (int q = 0; q < 3; q++) {
            int idx = tid + q * 256;
            int i = idx >> 4;
            int d4 = (idx & 15) * 4;
            float4 cv = make_float4(0.f, 0.f, 0.f, 0.f);
#pragma unroll 8
            for (int jq = 0; jq < TSRC; jq++) {
                float a = Sc[i][jq];
                float4 hv = *(const float4*)&Hs[jq][d4];
                cv.x = fmaf(a, hv.x, cv.x); cv.y = fmaf(a, hv.y, cv.y);
                cv.z = fmaf(a, hv.z, cv.z); cv.w = fmaf(a, hv.w, cv.w);
            }
            *(float4*)&ctx[(size_t)i * S + b * D + kc * 64 + d4] = cv;
        }
        __syncthreads();
    }
}

// ---------------------------------------------------------------------------
extern "C" void kernel_launch(void* const* d_in, const int* in_sizes, int n_in,
                              void* d_out, int out_size)
{
    const int*   src  = (const int*)d_in[0];
    const int*   tgt  = (const int*)d_in[1];
    const float* U    = (const float*)d_in[2];
    const float* Wz   = (const float*)d_in[3];
    const float* bz   = (const float*)d_in[4];
    const float* Wr   = (const float*)d_in[5];
    const float* br   = (const float*)d_in[6];
    const float* Wn   = (const float*)d_in[7];
    const float* bn   = (const float*)d_in[8];
    const float* Een  = (const float*)d_in[9];
    const float* Ede  = (const float*)d_in[10];
    const float* Wout = (const float*)d_in[11];
    const float* Wctx = (const float*)d_in[12];
    float* out = (float*)d_out;

    float *pWcat, *pbcat, *pUt, *pGenc, *pGdec, *ph1, *ph2, *pctx, *phall, *pout, *pW32;
    unsigned* pflags;
    cudaGetSymbolAddress((void**)&pWcat, g_Wcat);
    cudaGetSymbolAddress((void**)&pbcat, g_bcat);
    cudaGetSymbolAddress((void**)&pUt,   g_Ut);
    cudaGetSymbolAddress((void**)&pGenc, g_Genc);
    cudaGetSymbolAddress((void**)&pGdec, g_Gdec);
    cudaGetSymbolAddress((void**)&ph1,   g_h1);
    cudaGetSymbolAddress((void**)&ph2,   g_h2);
    cudaGetSymbolAddress((void**)&pctx,  g_ctx);
    cudaGetSymbolAddress((void**)&phall, g_hall);
    cudaGetSymbolAddress((void**)&pout,  g_out);
    cudaGetSymbolAddress((void**)&pW32,  g_Wout32);
    cudaGetSymbolAddress((void**)&pflags, g_flags);

    const int RECSMEM = 6 * RS * sizeof(float);   // 198,144 B
    cudaFuncSetAttribute(recurrence, cudaFuncAttributeMaxDynamicSharedMemorySize, RECSMEM);

    // 1-5: setup + gate precompute
    build_wcat<<<(1536 * D + 255) / 256, 256>>>(Wz, bz, Wr, br, Wn, bn);
    transpose512<<<dim3(16, 16), dim3(32, 8)>>>(U, pUt);
    zero2<<<(S + 255) / 256, 256>>>(ph1, ph2, S, pflags);
    sgemm_tf32<<<dim3(12, 24), 256>>>(nullptr, src, Een, pWcat, pbcat, nullptr,
                                      pGenc, M3, 1536, D, 0);
    sgemm_tf32<<<dim3(12, 24), 256>>>(nullptr, tgt, Ede, pWcat, pbcat, nullptr,
                                      pGdec, M3, 1536, D, 0);

    // 6 (ncu profiles this): the whole sequential chain
    recurrence<<<NGB * NGJ, 256, RECSMEM>>>(Wz, Wr, Wn, bz, br, bn);

    // 7-8: Wout tf32 pre-round, batched attention
    cvt_wout<<<(VDE * D / 4) / 256, 256>>>(Wout, pW32);
    attn_batched<<<BB, 256>>>(src, pctx);

    // 9: out-projection (writes tf32-rounded A for the logits GEMM)
    sgemm_tf32<<<dim3(4, 24), 256>>>(pctx, nullptr, nullptr, Wctx, nullptr, phall,
                                     pout, M3, D, D, 1);

    // 10: logits GEMM (256x128 tiles, cp.async pipeline)
    gemm_logits<<<dim3(250, 12), 512>>>(pout, pW32, out);
}